// round 1
// baseline (speedup 1.0000x reference)
#include <cuda_runtime.h>

static constexpr int NN = 100000;   // nodes
static constexpr int D  = 64;       // feature dim
static constexpr int NE = 1000000;  // edges

// Scratch (device globals — no allocation allowed in kernel_launch)
__device__ float g_h2 [NN * D];   // dinv[row] * (x @ W)
__device__ float g_acc[NN * D];   // edge-aggregation accumulator
__device__ float g_x  [NN * D];   // layer activations
__device__ float g_deg [NN];
__device__ float g_dinv[NN];
__device__ int   g_is64;

// ---------------------------------------------------------------------------
// Detect whether edge_index is int64 or int32 (JAX may silently downcast).
// For int64 little-endian values < 2^17, every odd 32-bit word is 0.
__global__ void detect_idx_width(const int* __restrict__ w) {
    __shared__ int s;
    if (threadIdx.x == 0) s = 0;
    __syncthreads();
    int v = 0;
    for (int i = threadIdx.x; i < 4096; i += blockDim.x) v |= w[2 * i + 1];
    if (v) atomicOr(&s, 1);
    __syncthreads();
    if (threadIdx.x == 0) g_is64 = (s == 0) ? 1 : 0;
}

__device__ __forceinline__ int edge_at(const void* ei, long long pos) {
    if (g_is64) return (int)((const long long*)ei)[pos];
    return ((const int*)ei)[pos];
}

// ---------------------------------------------------------------------------
__global__ void deg_init() {
    int i = blockIdx.x * 256 + threadIdx.x;
    if (i < NN) g_deg[i] = 1.0f;               // self-loop
}

__global__ void deg_count(const void* __restrict__ ei) {
    int e = blockIdx.x * 256 + threadIdx.x;
    if (e < NE) atomicAdd(&g_deg[edge_at(ei, (long long)NE + e)], 1.0f);
}

__global__ void dinv_kernel() {
    int i = blockIdx.x * 256 + threadIdx.x;
    if (i < NN) g_dinv[i] = rsqrtf(g_deg[i]);
}

// ---------------------------------------------------------------------------
// Y[row] = (bias? + ) (scale? dinv[row] : 1) * (X[row] @ W)   (64x64 W)
// Block: 256 threads, 64 rows per block, 4x4 register tile per thread.
__global__ void gemm64(const float* __restrict__ X, const float* __restrict__ W,
                       const float* __restrict__ bias, int use_scale,
                       float* __restrict__ Y) {
    __shared__ float xs[64 * 64];
    __shared__ float ws[64 * 64];
    const int tid  = threadIdx.x;
    const int base = blockIdx.x * 64;

    // load W (4096 floats)
    #pragma unroll
    for (int i = 0; i < 4; i++) {
        int idx = tid + i * 256;
        ((float4*)ws)[idx] = ((const float4*)W)[idx];
    }
    // load X tile (64 rows x 64 cols)
    #pragma unroll
    for (int i = 0; i < 4; i++) {
        int idx  = tid + i * 256;   // float4 index
        int row  = idx >> 4;
        int col4 = idx & 15;
        float4 v = make_float4(0.f, 0.f, 0.f, 0.f);
        if (base + row < NN)
            v = ((const float4*)X)[(long long)(base + row) * 16 + col4];
        ((float4*)xs)[idx] = v;
    }
    __syncthreads();

    const int r0 = (tid >> 4) << 2;
    const int c0 = (tid & 15) << 2;
    float acc[4][4] = {};
    #pragma unroll 8
    for (int k = 0; k < 64; k++) {
        float4 w4 = *(float4*)&ws[k * 64 + c0];
        #pragma unroll
        for (int i = 0; i < 4; i++) {
            float a = xs[(r0 + i) * 64 + k];
            acc[i][0] += a * w4.x;
            acc[i][1] += a * w4.y;
            acc[i][2] += a * w4.z;
            acc[i][3] += a * w4.w;
        }
    }

    #pragma unroll
    for (int i = 0; i < 4; i++) {
        int row = base + r0 + i;
        if (row < NN) {
            float s = use_scale ? g_dinv[row] : 1.0f;
            float4 o;
            o.x = acc[i][0] * s;
            o.y = acc[i][1] * s;
            o.z = acc[i][2] * s;
            o.w = acc[i][3] * s;
            if (bias) {
                o.x += bias[c0 + 0];
                o.y += bias[c0 + 1];
                o.z += bias[c0 + 2];
                o.w += bias[c0 + 3];
            }
            ((float4*)Y)[(long long)row * 16 + (c0 >> 2)] = o;
        }
    }
}

// ---------------------------------------------------------------------------
__global__ void zero_acc() {
    int i = blockIdx.x * 256 + threadIdx.x;
    if (i < NN * 16) ((float4*)g_acc)[i] = make_float4(0.f, 0.f, 0.f, 0.f);
}

// 16 threads per edge; each handles one float4 of the 64-float message.
__global__ void scatter(const void* __restrict__ ei) {
    long long t = (long long)blockIdx.x * 256 + threadIdx.x;
    int e    = (int)(t >> 4);
    int lane = (int)(t & 15);
    if (e >= NE) return;
    int src = edge_at(ei, e);
    int dst = edge_at(ei, (long long)NE + e);
    float4 v = *(const float4*)&g_h2[src * 64 + lane * 4];
    float* a = &g_acc[dst * 64 + lane * 4];
    asm volatile("red.global.add.v4.f32 [%0], {%1,%2,%3,%4};"
                 :: "l"(a), "f"(v.x), "f"(v.y), "f"(v.z), "f"(v.w)
                 : "memory");
}

// x' = relu(dinv[v] * (acc[v] + h2[v]) + b)   — self-loop folded (dinv*h2 = dinv^2*h)
__global__ void layer_epi(const float* __restrict__ bias) {
    int t = blockIdx.x * 256 + threadIdx.x;   // float4 index
    if (t >= NN * 16) return;
    int node = t >> 4;
    int c4   = (t & 15) << 2;
    float dv = g_dinv[node];
    float4 a = ((float4*)g_acc)[t];
    float4 h = ((float4*)g_h2)[t];
    float4 o;
    o.x = fmaxf(fmaf(dv, a.x + h.x, bias[c4 + 0]), 0.f);
    o.y = fmaxf(fmaf(dv, a.y + h.y, bias[c4 + 1]), 0.f);
    o.z = fmaxf(fmaf(dv, a.z + h.z, bias[c4 + 2]), 0.f);
    o.w = fmaxf(fmaf(dv, a.w + h.w, bias[c4 + 3]), 0.f);
    ((float4*)g_x)[t] = o;
}

// ---------------------------------------------------------------------------
extern "C" void kernel_launch(void* const* d_in, const int* in_sizes, int n_in,
                              void* d_out, int out_size) {
    const float* x    = (const float*)d_in[0];
    const void*  ei   = d_in[1];
    const float* Ws   = (const float*)d_in[2];
    const float* bs   = (const float*)d_in[3];
    const float* Wout = (const float*)d_in[4];
    const float* bout = (const float*)d_in[5];
    float* out = (float*)d_out;

    float *h2p, *xp;
    cudaGetSymbolAddress((void**)&h2p, g_h2);
    cudaGetSymbolAddress((void**)&xp,  g_x);

    const int GB_N   = (NN + 255) / 256;
    const int GB_E   = (NE + 255) / 256;
    const int GB_MM  = (NN + 63) / 64;
    const int GB_V4  = (NN * 16 + 255) / 256;
    const int GB_SC  = (int)(((long long)NE * 16 + 255) / 256);

    detect_idx_width<<<1, 256>>>((const int*)ei);
    deg_init<<<GB_N, 256>>>();
    deg_count<<<GB_E, 256>>>(ei);
    dinv_kernel<<<GB_N, 256>>>();

    const float* cur = x;
    for (int l = 0; l < 3; l++) {
        gemm64<<<GB_MM, 256>>>(cur, Ws + l * D * D, nullptr, 1, h2p);
        zero_acc<<<GB_V4, 256>>>();
        scatter<<<GB_SC, 256>>>(ei);
        layer_epi<<<GB_V4, 256>>>(bs + l * D);
        cur = xp;
    }
    gemm64<<<GB_MM, 256>>>(cur, Wout, bout, 0, out);
}

// round 2
// speedup vs baseline: 1.6380x; 1.6380x over previous
#include <cuda_runtime.h>

static constexpr int NN = 100000;   // nodes
static constexpr int D  = 64;       // feature dim
static constexpr int NE = 1000000;  // edges

static constexpr int SCAN_T = 512;
static constexpr int NSCB   = (NN + SCAN_T - 1) / SCAN_T;   // 196

// Scratch (device globals — no allocation allowed)
__device__ float g_h2 [NN * D];   // dinv[row] * (x @ W)
__device__ float g_x  [NN * D];   // layer activations
__device__ float g_dinv[NN];
__device__ int   g_degi[NN];
__device__ int   g_off [NN + 1];
__device__ int   g_cur [NN];
__device__ int   g_scan[NN];
__device__ int   g_bsum[NSCB];
__device__ int   g_csr [NE];      // src ids grouped by dst
__device__ int   g_is64;

// ---------------------------------------------------------------------------
// Detect whether edge_index is int64 or int32 (JAX may silently downcast).
// For int64 little-endian values < 2^17, every odd 32-bit word is 0.
__global__ void detect_idx_width(const int* __restrict__ w) {
    __shared__ int s;
    if (threadIdx.x == 0) s = 0;
    __syncthreads();
    int v = 0;
    for (int i = threadIdx.x; i < 4096; i += blockDim.x) v |= w[2 * i + 1];
    if (v) atomicOr(&s, 1);
    __syncthreads();
    if (threadIdx.x == 0) g_is64 = (s == 0) ? 1 : 0;
}

__device__ __forceinline__ int edge_at(const void* ei, long long pos) {
    if (g_is64) return (int)((const long long*)ei)[pos];
    return ((const int*)ei)[pos];
}

// ---------------------------------------------------------------------------
__global__ void degi_zero() {
    int i = blockIdx.x * 256 + threadIdx.x;
    if (i < NN) g_degi[i] = 0;
}

__global__ void degi_count(const void* __restrict__ ei) {
    int e = blockIdx.x * 256 + threadIdx.x;
    if (e < NE) atomicAdd(&g_degi[edge_at(ei, (long long)NE + e)], 1);
}

__global__ void dinv_kernel() {
    int i = blockIdx.x * 256 + threadIdx.x;
    if (i < NN) g_dinv[i] = rsqrtf(1.0f + (float)g_degi[i]);  // +1 self-loop
}

// ---- prefix scan (3 kernels) ----------------------------------------------
__global__ void scan1() {
    __shared__ int s[SCAN_T];
    int i = blockIdx.x * SCAN_T + threadIdx.x;
    int v = (i < NN) ? g_degi[i] : 0;
    s[threadIdx.x] = v;
    __syncthreads();
    #pragma unroll
    for (int off = 1; off < SCAN_T; off <<= 1) {
        int t = (threadIdx.x >= off) ? s[threadIdx.x - off] : 0;
        __syncthreads();
        s[threadIdx.x] += t;
        __syncthreads();
    }
    if (i < NN) g_scan[i] = s[threadIdx.x];
    if (threadIdx.x == SCAN_T - 1) g_bsum[blockIdx.x] = s[threadIdx.x];
}

__global__ void scan2() {   // one block of 256 threads; NSCB=196 <= 256
    __shared__ int s[256];
    int v = (threadIdx.x < NSCB) ? g_bsum[threadIdx.x] : 0;
    s[threadIdx.x] = v;
    __syncthreads();
    #pragma unroll
    for (int off = 1; off < 256; off <<= 1) {
        int t = (threadIdx.x >= off) ? s[threadIdx.x - off] : 0;
        __syncthreads();
        s[threadIdx.x] += t;
        __syncthreads();
    }
    if (threadIdx.x < NSCB) g_bsum[threadIdx.x] = s[threadIdx.x];
}

__global__ void scan3() {   // exclusive offsets + cursor init
    int i = blockIdx.x * 256 + threadIdx.x;
    if (i >= NN) return;
    int b = i / SCAN_T;
    int incl = g_scan[i] + (b > 0 ? g_bsum[b - 1] : 0);
    g_off[i + 1] = incl;
    if (i == 0) g_off[0] = 0;
    g_cur[i] = incl - g_degi[i];
}

__global__ void csr_fill(const void* __restrict__ ei) {
    int e = blockIdx.x * 256 + threadIdx.x;
    if (e >= NE) return;
    int src = edge_at(ei, e);
    int dst = edge_at(ei, (long long)NE + e);
    int pos = atomicAdd(&g_cur[dst], 1);
    g_csr[pos] = src;
}

// ---------------------------------------------------------------------------
// Y[row] = (bias? + ) (scale? dinv[row] : 1) * (X[row] @ W)   (64x64 W)
__global__ void __launch_bounds__(256) gemm64(
        const float* __restrict__ X, const float* __restrict__ W,
        const float* __restrict__ bias, int use_scale,
        float* __restrict__ Y) {
    __shared__ float xs[64 * 64];
    __shared__ float ws[64 * 64];
    const int tid  = threadIdx.x;
    const int base = blockIdx.x * 64;

    #pragma unroll
    for (int i = 0; i < 4; i++) {
        int idx = tid + i * 256;
        ((float4*)ws)[idx] = ((const float4*)W)[idx];
    }
    #pragma unroll
    for (int i = 0; i < 4; i++) {
        int idx  = tid + i * 256;
        int row  = idx >> 4;
        int col4 = idx & 15;
        float4 v = make_float4(0.f, 0.f, 0.f, 0.f);
        if (base + row < NN)
            v = ((const float4*)X)[(long long)(base + row) * 16 + col4];
        ((float4*)xs)[idx] = v;
    }
    __syncthreads();

    const int r0 = (tid >> 4) << 2;
    const int c0 = (tid & 15) << 2;
    float acc[4][4] = {};
    #pragma unroll 8
    for (int k = 0; k < 64; k++) {
        float4 w4 = *(float4*)&ws[k * 64 + c0];
        #pragma unroll
        for (int i = 0; i < 4; i++) {
            float a = xs[(r0 + i) * 64 + k];
            acc[i][0] += a * w4.x;
            acc[i][1] += a * w4.y;
            acc[i][2] += a * w4.z;
            acc[i][3] += a * w4.w;
        }
    }

    #pragma unroll
    for (int i = 0; i < 4; i++) {
        int row = base + r0 + i;
        if (row < NN) {
            float s = use_scale ? g_dinv[row] : 1.0f;
            float4 o;
            o.x = acc[i][0] * s;
            o.y = acc[i][1] * s;
            o.z = acc[i][2] * s;
            o.w = acc[i][3] * s;
            if (bias) {
                o.x += bias[c0 + 0];
                o.y += bias[c0 + 1];
                o.z += bias[c0 + 2];
                o.w += bias[c0 + 3];
            }
            ((float4*)Y)[(long long)row * 16 + (c0 >> 2)] = o;
        }
    }
}

// ---------------------------------------------------------------------------
// CSR gather + fused epilogue: x'[v] = relu(dinv[v]*(h2[v] + sum_nb h2[src]) + b)
// 16 threads per node, one float4 lane each.
__global__ void __launch_bounds__(256) gather_epi(const float* __restrict__ bias) {
    int t    = blockIdx.x * 256 + threadIdx.x;
    int node = t >> 4;
    if (node >= NN) return;
    int lane = t & 15;

    const float4* __restrict__ h2 = (const float4*)g_h2;
    int beg = g_off[node];
    int end = g_off[node + 1];

    float4 a = h2[node * 16 + lane];    // self-loop term (already dinv[v]-scaled)

    int e = beg;
    // 2x unrolled with index prefetch to expose MLP
    for (; e + 1 < end; e += 2) {
        int s0 = __ldg(&g_csr[e]);
        int s1 = __ldg(&g_csr[e + 1]);
        float4 v0 = h2[s0 * 16 + lane];
        float4 v1 = h2[s1 * 16 + lane];
        a.x += v0.x + v1.x;
        a.y += v0.y + v1.y;
        a.z += v0.z + v1.z;
        a.w += v0.w + v1.w;
    }
    if (e < end) {
        int s0 = __ldg(&g_csr[e]);
        float4 v0 = h2[s0 * 16 + lane];
        a.x += v0.x; a.y += v0.y; a.z += v0.z; a.w += v0.w;
    }

    float dv = g_dinv[node];
    float4 o;
    o.x = fmaxf(fmaf(dv, a.x, bias[lane * 4 + 0]), 0.f);
    o.y = fmaxf(fmaf(dv, a.y, bias[lane * 4 + 1]), 0.f);
    o.z = fmaxf(fmaf(dv, a.z, bias[lane * 4 + 2]), 0.f);
    o.w = fmaxf(fmaf(dv, a.w, bias[lane * 4 + 3]), 0.f);
    ((float4*)g_x)[t] = o;
}

// ---------------------------------------------------------------------------
extern "C" void kernel_launch(void* const* d_in, const int* in_sizes, int n_in,
                              void* d_out, int out_size) {
    const float* x    = (const float*)d_in[0];
    const void*  ei   = d_in[1];
    const float* Ws   = (const float*)d_in[2];
    const float* bs   = (const float*)d_in[3];
    const float* Wout = (const float*)d_in[4];
    const float* bout = (const float*)d_in[5];
    float* out = (float*)d_out;

    float *h2p, *xp;
    cudaGetSymbolAddress((void**)&h2p, g_h2);
    cudaGetSymbolAddress((void**)&xp,  g_x);

    const int GB_N  = (NN + 255) / 256;
    const int GB_E  = (NE + 255) / 256;
    const int GB_MM = (NN + 63) / 64;
    const int GB_G  = (NN * 16 + 255) / 256;

    detect_idx_width<<<1, 256>>>((const int*)ei);
    degi_zero<<<GB_N, 256>>>();
    degi_count<<<GB_E, 256>>>(ei);
    dinv_kernel<<<GB_N, 256>>>();
    scan1<<<NSCB, SCAN_T>>>();
    scan2<<<1, 256>>>();
    scan3<<<GB_N, 256>>>();
    csr_fill<<<GB_E, 256>>>(ei);

    const float* cur = x;
    for (int l = 0; l < 3; l++) {
        gemm64<<<GB_MM, 256>>>(cur, Ws + l * D * D, nullptr, 1, h2p);
        gather_epi<<<GB_G, 256>>>(bs + l * D);
        cur = xp;
    }
    gemm64<<<GB_MM, 256>>>(cur, Wout, bout, 0, out);
}